// round 1
// baseline (speedup 1.0000x reference)
#include <cuda_runtime.h>

#define BSZ 128
#define TN  512
#define UN  1024
#define ON  1024
#define TP1 513

// Scratch (static device globals — no allocation in kernel_launch)
__device__ float g_E [(size_t)TN * BSZ * UN];        // [t*128+b, 1024]
__device__ float g_ZK[(size_t)TN * BSZ * 4 * UN];    // [t*128+b, 4096]  (= E@W_k + b_r)
__device__ float g_H [(size_t)(TN + 1) * BSZ * UN];  // slot 0 = h0, slot t+1 = h after step t
__device__ float g_C [(size_t)BSZ * UN];

__global__ void init_state_kernel(const float* __restrict__ h0, const float* __restrict__ c0) {
    int i = blockIdx.x * blockDim.x + threadIdx.x;
    if (i < BSZ * UN) { g_H[i] = h0[i]; g_C[i] = c0[i]; }
}

// Generic fused SGEMM: C = A[M,1024] @ Bw[1024,N] + bias, tile 128x128x16, 256 thr, 8x8/thread.
// mode 0: A = target_inputs (row r -> b=r&127,t=r>>7, stride 513*1024), relu, C row-major N
// mode 1: A = g_E contiguous, C row-major N (=4096)
// mode 2: A = g_H+1slot contiguous, C = d_out scattered (row r=t*128+b -> [b,t,:])
__global__ __launch_bounds__(256) void sgemm_fused(
    const float* __restrict__ A, const float* __restrict__ Bw,
    const float* __restrict__ bias, float* __restrict__ C,
    int N, int mode)
{
    __shared__ float As[16][128];
    __shared__ float Bs[16][128];

    const int tid = threadIdx.x;
    const int bm = blockIdx.y, bn = blockIdx.x;

    // A-tile load mapping: thread loads 2 float4 from one row
    const int arow = bm * 128 + (tid >> 1);
    const int akoff = (tid & 1) * 8;
    const float* Aptr;
    if (mode == 0) {
        int b = arow & 127, t = arow >> 7;
        Aptr = A + ((size_t)b * TP1 + (size_t)t) * 1024;
    } else {
        Aptr = A + (size_t)arow * 1024;
    }

    // B-tile load mapping: thread loads 2 float4 from row kk=tid>>4
    const int bkk = tid >> 4;
    const int bn4 = (tid & 15) * 8;

    // compute mapping
    const int tm = (tid >> 4) * 8;
    const int tn = (tid & 15) * 8;

    float acc[8][8];
#pragma unroll
    for (int i = 0; i < 8; i++)
#pragma unroll
        for (int j = 0; j < 8; j++) acc[i][j] = 0.f;

    for (int k0 = 0; k0 < 1024; k0 += 16) {
        float4 a0 = *(const float4*)(Aptr + k0 + akoff);
        float4 a1 = *(const float4*)(Aptr + k0 + akoff + 4);
        const float* bsrc = Bw + (size_t)(k0 + bkk) * N + (size_t)bn * 128 + bn4;
        float4 b0 = *(const float4*)(bsrc);
        float4 b1 = *(const float4*)(bsrc + 4);

        __syncthreads();
        {
            int am = tid >> 1;
            As[akoff + 0][am] = a0.x; As[akoff + 1][am] = a0.y;
            As[akoff + 2][am] = a0.z; As[akoff + 3][am] = a0.w;
            As[akoff + 4][am] = a1.x; As[akoff + 5][am] = a1.y;
            As[akoff + 6][am] = a1.z; As[akoff + 7][am] = a1.w;
            *(float4*)&Bs[bkk][bn4]     = b0;
            *(float4*)&Bs[bkk][bn4 + 4] = b1;
        }
        __syncthreads();

#pragma unroll
        for (int kk = 0; kk < 16; kk++) {
            float a[8], b[8];
            *(float4*)(a)     = *(const float4*)&As[kk][tm];
            *(float4*)(a + 4) = *(const float4*)&As[kk][tm + 4];
            *(float4*)(b)     = *(const float4*)&Bs[kk][tn];
            *(float4*)(b + 4) = *(const float4*)&Bs[kk][tn + 4];
#pragma unroll
            for (int i = 0; i < 8; i++)
#pragma unroll
                for (int j = 0; j < 8; j++)
                    acc[i][j] += a[i] * b[j];
        }
    }

    const int grow0 = bm * 128 + tm;
    const int gcol0 = bn * 128 + tn;
    float bv[8];
#pragma unroll
    for (int j = 0; j < 8; j++) bv[j] = bias[gcol0 + j];

#pragma unroll
    for (int i = 0; i < 8; i++) {
        int r = grow0 + i;
        float o[8];
#pragma unroll
        for (int j = 0; j < 8; j++) {
            float v = acc[i][j] + bv[j];
            if (mode == 0) v = v > 0.f ? v : 0.f;
            o[j] = v;
        }
        float* dst;
        if (mode == 2) {
            int b = r & 127, t = r >> 7;
            dst = C + ((size_t)b * TN + (size_t)t) * 1024 + gcol0;
        } else {
            dst = C + (size_t)r * N + gcol0;
        }
        *(float4*)(dst)     = *(const float4*)(o);
        *(float4*)(dst + 4) = *(const float4*)(o + 4);
    }
}

__device__ __forceinline__ float sigmoidf_(float x) { return 1.f / (1.f + expf(-x)); }

// One recurrent step: z = ZK[t] + h_{t} @ W_r (4 gate segments computed together),
// gate math, update c in place, write h_{t+1}.
// Grid: 128 CTAs (each owns 8 gate-columns x all 4 gates x 128 rows), 256 threads.
__global__ __launch_bounds__(256) void lstm_step_kernel(const float* __restrict__ Wr, int t)
{
    __shared__ float hs[32][128];     // [k][row]
    __shared__ float ws[4][32][8];    // [gate][k][col]

    const int tid = threadIdx.x;
    const int j0 = blockIdx.x * 8;

    const float* __restrict__ Hprev = g_H + (size_t)t * (BSZ * UN);

    // h-tile load: thread -> row tid>>1, 16 k-floats at (tid&1)*16
    const int hrow = tid >> 1;
    const int hkoff = (tid & 1) * 16;
    // w-tile load: (g, kk, q) from tid
    const int wg_ = tid >> 6;
    const int wkk = (tid >> 1) & 31;
    const int wq = tid & 1;

    // compute mapping: col j, row quad rq
    const int j = tid & 7;
    const int rq = tid >> 3;

    float ai[4] = {0.f, 0.f, 0.f, 0.f};
    float af[4] = {0.f, 0.f, 0.f, 0.f};
    float ag[4] = {0.f, 0.f, 0.f, 0.f};
    float ao[4] = {0.f, 0.f, 0.f, 0.f};

    for (int k0 = 0; k0 < 1024; k0 += 32) {
        float4 hv[4];
#pragma unroll
        for (int q = 0; q < 4; q++)
            hv[q] = *(const float4*)(Hprev + (size_t)hrow * 1024 + k0 + hkoff + q * 4);
        float4 wv = *(const float4*)(Wr + (size_t)(k0 + wkk) * 4096 + (size_t)wg_ * 1024 + j0 + wq * 4);

        __syncthreads();
#pragma unroll
        for (int q = 0; q < 4; q++) {
            hs[hkoff + q * 4 + 0][hrow] = hv[q].x;
            hs[hkoff + q * 4 + 1][hrow] = hv[q].y;
            hs[hkoff + q * 4 + 2][hrow] = hv[q].z;
            hs[hkoff + q * 4 + 3][hrow] = hv[q].w;
        }
        *(float4*)&ws[wg_][wkk][wq * 4] = wv;
        __syncthreads();

#pragma unroll
        for (int kk = 0; kk < 32; kk++) {
            float4 h4 = *(const float4*)&hs[kk][rq * 4];
            float wi = ws[0][kk][j];
            float wf = ws[1][kk][j];
            float wg2 = ws[2][kk][j];
            float wo = ws[3][kk][j];
            ai[0] += h4.x * wi; ai[1] += h4.y * wi; ai[2] += h4.z * wi; ai[3] += h4.w * wi;
            af[0] += h4.x * wf; af[1] += h4.y * wf; af[2] += h4.z * wf; af[3] += h4.w * wf;
            ag[0] += h4.x * wg2; ag[1] += h4.y * wg2; ag[2] += h4.z * wg2; ag[3] += h4.w * wg2;
            ao[0] += h4.x * wo; ao[1] += h4.y * wo; ao[2] += h4.z * wo; ao[3] += h4.w * wo;
        }
    }

    float* __restrict__ Hnew = g_H + (size_t)(t + 1) * (BSZ * UN);
    const float* __restrict__ zkb = g_ZK + (size_t)t * BSZ * 4096;

#pragma unroll
    for (int i = 0; i < 4; i++) {
        int r = rq * 4 + i;
        size_t zo = (size_t)r * 4096 + j0 + j;
        float zi = ai[i] + zkb[zo];
        float zf = af[i] + zkb[zo + 1024];
        float zg = ag[i] + zkb[zo + 2048];
        float zoo = ao[i] + zkb[zo + 3072];
        size_t ci = (size_t)r * 1024 + j0 + j;
        float c = g_C[ci];
        float si = sigmoidf_(zi);
        float sf = sigmoidf_(zf);
        float so = sigmoidf_(zoo);
        float cn = sf * c + si * tanhf(zg);
        float hn = so * tanhf(cn);
        g_C[ci] = cn;
        Hnew[ci] = hn;
    }
}

extern "C" void kernel_launch(void* const* d_in, const int* in_sizes, int n_in,
                              void* d_out, int out_size)
{
    const float* h0    = (const float*)d_in[0];
    const float* c0    = (const float*)d_in[1];
    const float* X     = (const float*)d_in[2];   // [128, 513, 1024]
    const float* W_emb = (const float*)d_in[3];   // [1024, 1024]
    const float* b_emb = (const float*)d_in[4];
    const float* W_k   = (const float*)d_in[5];   // [1024, 4096]
    const float* W_r   = (const float*)d_in[6];   // [1024, 4096]
    const float* b_r   = (const float*)d_in[7];   // [4096]
    const float* W_out = (const float*)d_in[8];   // [1024, 1024]
    const float* b_out = (const float*)d_in[9];
    (void)in_sizes; (void)n_in; (void)out_size;

    float *pE, *pZK, *pH;
    cudaGetSymbolAddress((void**)&pE, g_E);
    cudaGetSymbolAddress((void**)&pZK, g_ZK);
    cudaGetSymbolAddress((void**)&pH, g_H);

    // 1. state init
    init_state_kernel<<<(BSZ * UN + 255) / 256, 256>>>(h0, c0);

    // 2. E = relu(X @ W_emb + b_emb), all timesteps batched  (M=65536, N=1024)
    {
        dim3 grid(1024 / 128, (TN * BSZ) / 128);
        sgemm_fused<<<grid, 256>>>(X, W_emb, b_emb, pE, 1024, 0);
    }

    // 3. ZK = E @ W_k + b_r, all timesteps batched  (M=65536, N=4096)
    {
        dim3 grid(4096 / 128, (TN * BSZ) / 128);
        sgemm_fused<<<grid, 256>>>(pE, W_k, b_r, pZK, 4096, 1);
    }

    // 4. sequential recurrence (only h @ W_r + pointwise on the critical path)
    for (int t = 0; t < TN; t++) {
        lstm_step_kernel<<<128, 256>>>(W_r, t);
    }

    // 5. OUT = H @ W_out + b_out, all timesteps batched  (M=65536, N=1024)
    {
        dim3 grid(1024 / 128, (TN * BSZ) / 128);
        sgemm_fused<<<grid, 256>>>(pH + (size_t)BSZ * UN, W_out, b_out, (float*)d_out, 1024, 2);
    }
}